// round 10
// baseline (speedup 1.0000x reference)
#include <cuda_runtime.h>
#include <cuda_bf16.h>
#include <math.h>
#include <cstdint>

// NT-Xent loss via mma.sync bf16 HMMA, split-tile software pipeline:
// epilogue (MUFU ex2 + FFMA reduce) of one 64-col half interleaves with the
// MMA stream of the next half so tensor and MUFU pipes overlap.
//   K1 normalize: z_i,z_j -> g_znh [N,128] bf16 row-l2-normalized
//   K2 simloss  : 128-row x 4096-col chunk per CTA (CS=2 col split)
//   K3 finalize : combine partials, mean -> d_out[0]

#define D_DIM     128
#define N_MAX     8192
#define CS        2
#define LOG2E_X2  2.885390081777927f   // 2*log2(e): folds /T=0.5 into exp2

__device__ __nv_bfloat16 g_znh[N_MAX * D_DIM];
__device__ float g_sumexp[CS * N_MAX];
__device__ float g_pos[CS * N_MAX];

// ------------------------------------------------------------- helpers
__device__ __forceinline__ uint32_t smem_u32(const void* p) {
    uint32_t a;
    asm("{ .reg .u64 t; cvta.to.shared.u64 t, %1; cvt.u32.u64 %0, t; }" : "=r"(a) : "l"(p));
    return a;
}
__device__ __forceinline__ void cp_async16(uint32_t saddr, const void* gaddr) {
    asm volatile("cp.async.cg.shared.global [%0], [%1], 16;" :: "r"(saddr), "l"(gaddr));
}
#define CP_COMMIT() asm volatile("cp.async.commit_group;" ::: "memory")
#define CP_WAIT(n)  asm volatile("cp.async.wait_group %0;" :: "n"(n) : "memory")

__device__ __forceinline__ void ldsm_x4(uint32_t* r, uint32_t addr) {
    asm volatile("ldmatrix.sync.aligned.m8n8.x4.shared.b16 {%0,%1,%2,%3}, [%4];"
                 : "=r"(r[0]), "=r"(r[1]), "=r"(r[2]), "=r"(r[3]) : "r"(addr));
}
__device__ __forceinline__ void mma16816(float* d, const uint32_t* a, const uint32_t* b) {
    asm volatile(
        "mma.sync.aligned.m16n8k16.row.col.f32.bf16.bf16.f32 "
        "{%0,%1,%2,%3}, {%4,%5,%6,%7}, {%8,%9}, {%0,%1,%2,%3};"
        : "+f"(d[0]), "+f"(d[1]), "+f"(d[2]), "+f"(d[3])
        : "r"(a[0]), "r"(a[1]), "r"(a[2]), "r"(a[3]), "r"(b[0]), "r"(b[1]));
}
__device__ __forceinline__ float ex2(float x) {
    float e;
    asm("ex2.approx.ftz.f32 %0, %1;" : "=f"(e) : "f"(x));
    return e;
}

// smem tile: 128 rows x 256B (128 bf16); 16B chunks swizzled c^(row&7).
__device__ __forceinline__ uint32_t tile_addr(uint32_t base, int row, int chunk) {
    return base + row * 256 + (((uint32_t)(chunk ^ (row & 7))) << 4);
}

// ------------------------------------------------------------- K1
__global__ void ntx_normalize(const float* __restrict__ zi,
                              const float* __restrict__ zj, int Bv) {
    int warp = (blockIdx.x * blockDim.x + threadIdx.x) >> 5;
    int lane = threadIdx.x & 31;
    int Nv = 2 * Bv;
    if (warp >= Nv) return;
    const float* src = (warp < Bv) ? (zi + (size_t)warp * D_DIM)
                                   : (zj + (size_t)(warp - Bv) * D_DIM);
    float4 v = ((const float4*)src)[lane];
    float ss = v.x * v.x + v.y * v.y + v.z * v.z + v.w * v.w;
#pragma unroll
    for (int o = 16; o; o >>= 1) ss += __shfl_xor_sync(0xFFFFFFFFu, ss, o);
    float rn = 1.0f / fmaxf(sqrtf(ss), 1e-12f);
    __nv_bfloat162 p0 = __float22bfloat162_rn(make_float2(v.x * rn, v.y * rn));
    __nv_bfloat162 p1 = __float22bfloat162_rn(make_float2(v.z * rn, v.w * rn));
    uint2 out;
    out.x = *(uint32_t*)&p0;
    out.y = *(uint32_t*)&p1;
    ((uint2*)(g_znh + (size_t)warp * D_DIM))[lane] = out;
}

// ------------------------------------------------------------- K2
#define A_OFF    0
#define B0_OFF   32768
#define B1_OFF   65536
#define RED_OFF  98304
#define SMEM_REQ 101376

__device__ __forceinline__ void issue_tile_loads(uint32_t sdst, int srcRow, int tid) {
    int r = tid >> 1, h = tid & 1;
    const char* g = (const char*)(g_znh + (size_t)(srcRow + r) * D_DIM + h * 64);
    uint32_t srow = sdst + r * 256;
#pragma unroll
    for (int i = 0; i < 8; i++) {
        int c = h * 8 + i;
        cp_async16(srow + (((uint32_t)(c ^ (r & 7))) << 4), g + i * 16);
    }
}

// Epilogue for one (mt, ntl) chunk of a 64-col half accumulator.
// i = 0..7 -> mt = i&1, ntl = i>>1. gate: 0 neutralizes (first deferred half).
__device__ __forceinline__ void epi_chunk(
    const float (&acc)[2][4][4], int i, int ntbase,
    bool isDiag, bool isPos, float gate,
    int wm, int wn, int lane,
    float (&rAcc)[2][2], float (&rPos)[2][2])
{
    const int mt = i & 1, ntl = i >> 1;
    if (!isDiag && !isPos) {
        float e0 = ex2(acc[mt][ntl][0] * LOG2E_X2) + ex2(acc[mt][ntl][1] * LOG2E_X2);
        float e1 = ex2(acc[mt][ntl][2] * LOG2E_X2) + ex2(acc[mt][ntl][3] * LOG2E_X2);
        rAcc[mt][0] = fmaf(gate, e0, rAcc[mt][0]);
        rAcc[mt][1] = fmaf(gate, e1, rAcc[mt][1]);
    } else {
        // diag/pos tiles are never the gated (first) deferred half: gate==1 here
        int r0 = wm + mt * 16 + (lane >> 2);
        int c0 = wn + (ntbase + ntl) * 8 + 2 * (lane & 3);
#pragma unroll
        for (int e = 0; e < 4; e++) {
            int r = r0 + ((e >> 1) << 3);
            int c = c0 + (e & 1);
            float v = acc[mt][ntl][e];
            float ev = ex2(v * LOG2E_X2);
            bool hit = (r == c);
            float* ra = &rAcc[mt][e >> 1];
            if (isDiag) { if (!hit) *ra += ev; }
            else { *ra += ev; if (hit) rPos[mt][e >> 1] += v * 2.0f; }
        }
    }
}

__global__ __launch_bounds__(256, 1) void ntx_simloss(int Bv) {
    extern __shared__ char smraw[];
    uint32_t raw = smem_u32(smraw);
    uint32_t base = (raw + 1023u) & ~1023u;
    char* abase = smraw + (base - raw);

    const int tid = threadIdx.x, lane = tid & 31, wid = tid >> 5;
    const int Nv = 2 * Bv;
    const int rowGroup = blockIdx.x >> 1, cs = blockIdx.x & 1;
    const int rowStart = rowGroup * 128;
    const int chunkN = Nv / CS, colStart = cs * chunkN;
    const int Tiles = chunkN / 128;                    // 32

    const int wm = (wid & 3) * 32;                     // warp row offset
    const int wn = (wid >> 2) * 64;                    // warp col offset

    issue_tile_loads(base + A_OFF, rowStart, tid);
    issue_tile_loads(base + B0_OFF, colStart, tid);
    CP_COMMIT();

    int cpos = rowStart + Bv; if (cpos >= Nv) cpos -= Nv;
    const int diagTile = (rowStart - colStart >= 0 && rowStart - colStart < chunkN)
                             ? (rowStart - colStart) >> 7 : -1;
    const int posTile = (cpos - colStart >= 0 && cpos - colStart < chunkN)
                            ? (cpos - colStart) >> 7 : -1;

    float rAcc[2][2] = {{0.f, 0.f}, {0.f, 0.f}};
    float rPos[2][2] = {{0.f, 0.f}, {0.f, 0.f}};

    float accA[2][4][4];   // half 0 (cols wn+0..31) of current tile
    float accB[2][4][4];   // half 1 (cols wn+32..63); epilogue deferred 1 tile
#pragma unroll
    for (int mt = 0; mt < 2; mt++)
#pragma unroll
        for (int nt = 0; nt < 4; nt++)
#pragma unroll
            for (int e = 0; e < 4; e++) accB[mt][nt][e] = 0.f;

    bool dfDiag = false, dfPos = false;
    float dfGate = 0.f;

    for (int ct = 0; ct < Tiles; ct++) {
        if (ct + 1 < Tiles)
            issue_tile_loads(base + (((ct + 1) & 1) ? B1_OFF : B0_OFF),
                             colStart + (ct + 1) * 128, tid);
        CP_COMMIT();
        CP_WAIT(1);
        __syncthreads();

        const uint32_t Bb = base + ((ct & 1) ? B1_OFF : B0_OFF);
        const bool tDiag = (ct == diagTile), tPos = (ct == posTile);

        // ---- loop1: MMA half0 (np 0,1) + deferred epilogue of accB(ct-1)
        float accN[2][4][4];
#pragma unroll
        for (int mt = 0; mt < 2; mt++)
#pragma unroll
            for (int nt = 0; nt < 4; nt++)
#pragma unroll
                for (int e = 0; e < 4; e++) accN[mt][nt][e] = 0.f;
#pragma unroll
        for (int ks = 0; ks < 8; ks++) {
            uint32_t a[2][4];
#pragma unroll
            for (int mt = 0; mt < 2; mt++)
                ldsm_x4(a[mt], tile_addr(base + A_OFF,
                                         wm + mt * 16 + (lane & 15),
                                         ks * 2 + (lane >> 4)));
            uint32_t b[2][4];
#pragma unroll
            for (int npl = 0; npl < 2; npl++)
                ldsm_x4(b[npl], tile_addr(Bb,
                                          wn + (npl * 2 + (lane >> 4)) * 8 + (lane & 7),
                                          ks * 2 + ((lane >> 3) & 1)));
#pragma unroll
            for (int mt = 0; mt < 2; mt++)
#pragma unroll
                for (int npl = 0; npl < 2; npl++) {
                    mma16816(accN[mt][npl * 2],     a[mt], &b[npl][0]);
                    mma16816(accN[mt][npl * 2 + 1], a[mt], &b[npl][2]);
                }
            epi_chunk(accB, ks, 4, dfDiag, dfPos, dfGate, wm, wn, lane, rAcc, rPos);
        }
#pragma unroll
        for (int mt = 0; mt < 2; mt++)
#pragma unroll
            for (int nt = 0; nt < 4; nt++)
#pragma unroll
                for (int e = 0; e < 4; e++) accA[mt][nt][e] = accN[mt][nt][e];

        // ---- loop2: MMA half1 (np 2,3) + epilogue of accA(ct)
#pragma unroll
        for (int mt = 0; mt < 2; mt++)
#pragma unroll
            for (int nt = 0; nt < 4; nt++)
#pragma unroll
                for (int e = 0; e < 4; e++) accB[mt][nt][e] = 0.f;
#pragma unroll
        for (int ks = 0; ks < 8; ks++) {
            uint32_t a[2][4];
#pragma unroll
            for (int mt = 0; mt < 2; mt++)
                ldsm_x4(a[mt], tile_addr(base + A_OFF,
                                         wm + mt * 16 + (lane & 15),
                                         ks * 2 + (lane >> 4)));
            uint32_t b[2][4];
#pragma unroll
            for (int npl = 0; npl < 2; npl++)
                ldsm_x4(b[npl], tile_addr(Bb,
                                          wn + ((npl + 2) * 2 + (lane >> 4)) * 8 + (lane & 7),
                                          ks * 2 + ((lane >> 3) & 1)));
#pragma unroll
            for (int mt = 0; mt < 2; mt++)
#pragma unroll
                for (int npl = 0; npl < 2; npl++) {
                    mma16816(accB[mt][npl * 2],     a[mt], &b[npl][0]);
                    mma16816(accB[mt][npl * 2 + 1], a[mt], &b[npl][2]);
                }
            epi_chunk(accA, ks, 0, tDiag, tPos, 1.0f, wm, wn, lane, rAcc, rPos);
        }

        dfDiag = tDiag; dfPos = tPos; dfGate = 1.0f;
        __syncthreads();
    }

    // tail: epilogue of last tile's half1
#pragma unroll
    for (int i = 0; i < 8; i++)
        epi_chunk(accB, i, 4, dfDiag, dfPos, dfGate, wm, wn, lane, rAcc, rPos);

    // reduce across 4-lane col groups, then across the two n-warp halves
    float* rowSum = (float*)(abase + RED_OFF);        // [2][128]
    float* rowPos = rowSum + 256;                     // [2][128]
#pragma unroll
    for (int mt = 0; mt < 2; mt++)
#pragma unroll
        for (int h = 0; h < 2; h++) {
            float v = rAcc[mt][h], pv = rPos[mt][h];
            v += __shfl_xor_sync(0xFFFFFFFFu, v, 1);
            v += __shfl_xor_sync(0xFFFFFFFFu, v, 2);
            pv += __shfl_xor_sync(0xFFFFFFFFu, pv, 1);
            pv += __shfl_xor_sync(0xFFFFFFFFu, pv, 2);
            if ((lane & 3) == 0) {
                int r = wm + mt * 16 + h * 8 + (lane >> 2);
                rowSum[(wid >> 2) * 128 + r] = v;
                rowPos[(wid >> 2) * 128 + r] = pv;
            }
        }
    __syncthreads();
    if (tid < 128) {
        g_sumexp[cs * Nv + rowStart + tid] = rowSum[tid] + rowSum[128 + tid];
        g_pos[cs * Nv + rowStart + tid]    = rowPos[tid] + rowPos[128 + tid];
    }
}

// ------------------------------------------------------------- K3
__global__ void ntx_finalize(float* __restrict__ out, int Bv) {
    const int Nv = 2 * Bv;
    __shared__ float red[256];
    float acc = 0.f;
    for (int r = threadIdx.x; r < Nv; r += blockDim.x) {
        float se = 0.f, p = 0.f;
#pragma unroll
        for (int c = 0; c < CS; c++) {
            se += g_sumexp[c * Nv + r];
            p  += g_pos[c * Nv + r];
        }
        acc += (logf(se) - p);
    }
    red[threadIdx.x] = acc;
    __syncthreads();
    for (int s = 128; s > 0; s >>= 1) {
        if (threadIdx.x < s) red[threadIdx.x] += red[threadIdx.x + s];
        __syncthreads();
    }
    if (threadIdx.x == 0) out[0] = red[0] / (float)Nv;
}

// ------------------------------------------------------------- launch
extern "C" void kernel_launch(void* const* d_in, const int* in_sizes, int n_in,
                              void* d_out, int out_size) {
    const float* zi = (const float*)d_in[0];
    const float* zj = (const float*)d_in[1];
    const int Bv = in_sizes[0] / D_DIM;   // 4096
    const int Nv = 2 * Bv;                // 8192

    cudaFuncSetAttribute(ntx_simloss, cudaFuncAttributeMaxDynamicSharedMemorySize, SMEM_REQ);

    ntx_normalize<<<Nv / 8, 256>>>(zi, zj, Bv);
    ntx_simloss<<<(Nv / 128) * CS, 256, SMEM_REQ>>>(Bv);
    ntx_finalize<<<1, 256>>>((float*)d_out, Bv);
}

// round 14
// speedup vs baseline: 1.2366x; 1.2366x over previous
#include <cuda_runtime.h>
#include <cuda_bf16.h>
#include <math.h>
#include <cstdint>

// NT-Xent loss via mma.sync bf16 HMMA, SYMMETRY-PACKED: only upper-triangle
// 128x128 tiles are computed (1.97x less tensor work). Each tile's exp values
// feed row sums (block I) and column sums (block J, shfl+atomicAdd flush).
//   K1 normalize: z -> g_znh bf16, also zeroes accumulators
//   K2 simloss  : 32 strips (rowgroup pair I,63-I; 65 tiles) x 4 CTAs = 128 CTAs
//   K3 finalize : mean(log(sumexp) - pos) -> d_out[0]

#define D_DIM     128
#define N_MAX     8192
#define LOG2E_X2  2.885390081777927f   // 2*log2(e): folds /T=0.5 into exp2

__device__ __nv_bfloat16 g_znh[N_MAX * D_DIM];
__device__ float g_sumexp[N_MAX];
__device__ float g_pos[N_MAX];

// ------------------------------------------------------------- helpers
__device__ __forceinline__ uint32_t smem_u32(const void* p) {
    uint32_t a;
    asm("{ .reg .u64 t; cvta.to.shared.u64 t, %1; cvt.u32.u64 %0, t; }" : "=r"(a) : "l"(p));
    return a;
}
__device__ __forceinline__ void cp_async16(uint32_t saddr, const void* gaddr) {
    asm volatile("cp.async.cg.shared.global [%0], [%1], 16;" :: "r"(saddr), "l"(gaddr));
}
#define CP_COMMIT() asm volatile("cp.async.commit_group;" ::: "memory")
#define CP_WAIT(n)  asm volatile("cp.async.wait_group %0;" :: "n"(n) : "memory")

__device__ __forceinline__ void ldsm_x4(uint32_t* r, uint32_t addr) {
    asm volatile("ldmatrix.sync.aligned.m8n8.x4.shared.b16 {%0,%1,%2,%3}, [%4];"
                 : "=r"(r[0]), "=r"(r[1]), "=r"(r[2]), "=r"(r[3]) : "r"(addr));
}
__device__ __forceinline__ void mma16816(float* d, const uint32_t* a, const uint32_t* b) {
    asm volatile(
        "mma.sync.aligned.m16n8k16.row.col.f32.bf16.bf16.f32 "
        "{%0,%1,%2,%3}, {%4,%5,%6,%7}, {%8,%9}, {%0,%1,%2,%3};"
        : "+f"(d[0]), "+f"(d[1]), "+f"(d[2]), "+f"(d[3])
        : "r"(a[0]), "r"(a[1]), "r"(a[2]), "r"(a[3]), "r"(b[0]), "r"(b[1]));
}
__device__ __forceinline__ float ex2(float x) {
    float e;
    asm("ex2.approx.ftz.f32 %0, %1;" : "=f"(e) : "f"(x));
    return e;
}

// smem tile: 128 rows x 256B (128 bf16); 16B chunks swizzled c^(row&7).
__device__ __forceinline__ uint32_t tile_addr(uint32_t base, int row, int chunk) {
    return base + row * 256 + (((uint32_t)(chunk ^ (row & 7))) << 4);
}

// ------------------------------------------------------------- K1 (+ zero accums)
__global__ void ntx_normalize(const float* __restrict__ zi,
                              const float* __restrict__ zj, int Bv) {
    int gt = blockIdx.x * blockDim.x + threadIdx.x;
    int Nv = 2 * Bv;
    if (gt < Nv) { g_sumexp[gt] = 0.f; g_pos[gt] = 0.f; }
    int warp = gt >> 5;
    int lane = threadIdx.x & 31;
    if (warp >= Nv) return;
    const float* src = (warp < Bv) ? (zi + (size_t)warp * D_DIM)
                                   : (zj + (size_t)(warp - Bv) * D_DIM);
    float4 v = ((const float4*)src)[lane];
    float ss = v.x * v.x + v.y * v.y + v.z * v.z + v.w * v.w;
#pragma unroll
    for (int o = 16; o; o >>= 1) ss += __shfl_xor_sync(0xFFFFFFFFu, ss, o);
    float rn = 1.0f / fmaxf(sqrtf(ss), 1e-12f);
    __nv_bfloat162 p0 = __float22bfloat162_rn(make_float2(v.x * rn, v.y * rn));
    __nv_bfloat162 p1 = __float22bfloat162_rn(make_float2(v.z * rn, v.w * rn));
    uint2 out;
    out.x = *(uint32_t*)&p0;
    out.y = *(uint32_t*)&p1;
    ((uint2*)(g_znh + (size_t)warp * D_DIM))[lane] = out;
}

// ------------------------------------------------------------- K2
#define A0_OFF   0
#define A1_OFF   32768
#define B0_OFF   65536
#define B1_OFF   98304
#define SMEM_REQ 132096   // 4x32KB tiles + 1KB align pad

__device__ __forceinline__ void issue_tile_loads(uint32_t sdst, int srcRow, int tid) {
    int r = tid >> 1, h = tid & 1;
    const char* g = (const char*)(g_znh + (size_t)(srcRow + r) * D_DIM + h * 64);
    uint32_t srow = sdst + r * 256;
#pragma unroll
    for (int i = 0; i < 8; i++) {
        int c = h * 8 + i;
        cp_async16(srow + (((uint32_t)(c ^ (r & 7))) << 4), g + i * 16);
    }
}

__global__ __launch_bounds__(256, 1) void ntx_simloss(int Bv) {
    extern __shared__ char smraw[];
    uint32_t raw = smem_u32(smraw);
    uint32_t base = (raw + 1023u) & ~1023u;

    const int tid = threadIdx.x, lane = tid & 31, wid = tid >> 5;
    const int strip = blockIdx.x >> 2, q = blockIdx.x & 3;
    const int I0 = strip, I1 = 63 - strip;
    const int L0 = 64 - strip;                  // seg0 length (J = I0..63)
    const int lo = (q * 65) >> 2, hi = ((q + 1) * 65) >> 2;

    const int wm = (wid & 3) * 32;              // warp row offset in tile
    const int wn = (wid >> 2) * 64;             // warp col offset in tile

    // prologue: both A tiles + first B tile
    issue_tile_loads(base + A0_OFF, I0 * 128, tid);
    issue_tile_loads(base + A1_OFF, I1 * 128, tid);
    {
        int J = (lo < L0) ? I0 + lo : I1 + (lo - L0);
        issue_tile_loads(base + B0_OFF, J * 128, tid);
    }
    CP_COMMIT();

    float rAccS[2][2][2];                       // [seg][mt][rowhalf]
#pragma unroll
    for (int s = 0; s < 2; s++)
#pragma unroll
        for (int mt = 0; mt < 2; mt++) { rAccS[s][mt][0] = 0.f; rAccS[s][mt][1] = 0.f; }
    float cAcc[8][2];
#pragma unroll
    for (int nt = 0; nt < 8; nt++) { cAcc[nt][0] = 0.f; cAcc[nt][1] = 0.f; }

    for (int t = lo; t < hi; t++) {
        if (t + 1 < hi) {
            int Jn = (t + 1 < L0) ? I0 + (t + 1) : I1 + (t + 1 - L0);
            issue_tile_loads(base + (((t + 1 - lo) & 1) ? B1_OFF : B0_OFF), Jn * 128, tid);
        }
        CP_COMMIT();
        CP_WAIT(1);
        __syncthreads();

        const int seg = (t < L0) ? 0 : 1;
        const int I = seg ? I1 : I0;
        const int J = seg ? I1 + (t - L0) : I0 + t;
        const uint32_t Ab = base + (seg ? A1_OFF : A0_OFF);
        const uint32_t Bb = base + (((t - lo) & 1) ? B1_OFF : B0_OFF);
        const bool isDiag = (J == I);
        const bool isPos = (J == I + 32);

        // ---- MMA: acc[2][8][4] over 128x128 tile (warp: 32 rows x 64 cols)
        float acc[2][8][4];
#pragma unroll
        for (int mt = 0; mt < 2; mt++)
#pragma unroll
            for (int nt = 0; nt < 8; nt++)
#pragma unroll
                for (int e = 0; e < 4; e++) acc[mt][nt][e] = 0.f;

#pragma unroll
        for (int ks = 0; ks < 8; ks++) {
            uint32_t a[2][4];
#pragma unroll
            for (int mt = 0; mt < 2; mt++)
                ldsm_x4(a[mt], tile_addr(Ab, wm + mt * 16 + (lane & 15),
                                         ks * 2 + (lane >> 4)));
            uint32_t b[4][4];
#pragma unroll
            for (int np = 0; np < 4; np++)
                ldsm_x4(b[np], tile_addr(Bb,
                                         wn + (np * 2 + (lane >> 4)) * 8 + (lane & 7),
                                         ks * 2 + ((lane >> 3) & 1)));
#pragma unroll
            for (int mt = 0; mt < 2; mt++)
#pragma unroll
                for (int np = 0; np < 4; np++) {
                    mma16816(acc[mt][np * 2],     a[mt], &b[np][0]);
                    mma16816(acc[mt][np * 2 + 1], a[mt], &b[np][2]);
                }
        }

        // ---- epilogue
        if (!isDiag && !isPos) {
#pragma unroll
            for (int mt = 0; mt < 2; mt++)
#pragma unroll
                for (int nt = 0; nt < 8; nt++)
#pragma unroll
                    for (int e = 0; e < 4; e++) {
                        float ev = ex2(acc[mt][nt][e] * LOG2E_X2);
                        rAccS[seg][mt][e >> 1] += ev;
                        cAcc[nt][e & 1] += ev;
                    }
        } else if (isDiag) {
            // rows only; exclude self (local r==c); NO col contribution
#pragma unroll
            for (int mt = 0; mt < 2; mt++) {
                int r0 = wm + mt * 16 + (lane >> 2);
#pragma unroll
                for (int nt = 0; nt < 8; nt++) {
                    int c0 = wn + nt * 8 + 2 * (lane & 3);
#pragma unroll
                    for (int e = 0; e < 4; e++) {
                        int r = r0 + ((e >> 1) << 3);
                        int c = c0 + (e & 1);
                        float ev = ex2(acc[mt][nt][e] * LOG2E_X2);
                        if (r != c) rAccS[seg][mt][e >> 1] += ev;
                    }
                }
            }
        } else {  // pos tile (J == I+32): normal sums + pos extraction for BOTH groups
#pragma unroll
            for (int mt = 0; mt < 2; mt++) {
                int r0 = wm + mt * 16 + (lane >> 2);
#pragma unroll
                for (int nt = 0; nt < 8; nt++) {
                    int c0 = wn + nt * 8 + 2 * (lane & 3);
#pragma unroll
                    for (int e = 0; e < 4; e++) {
                        int r = r0 + ((e >> 1) << 3);
                        int c = c0 + (e & 1);
                        float v = acc[mt][nt][e];
                        float ev = ex2(v * LOG2E_X2);
                        rAccS[seg][mt][e >> 1] += ev;
                        cAcc[nt][e & 1] += ev;
                        if (r == c) {
                            float v2 = v * 2.0f;
                            atomicAdd(&g_pos[I * 128 + r], v2);
                            atomicAdd(&g_pos[J * 128 + r], v2);
                        }
                    }
                }
            }
        }

        // ---- column-sum flush (rows of group J); skip on diagonal tiles
        if (!isDiag) {
#pragma unroll
            for (int nt = 0; nt < 8; nt++)
#pragma unroll
                for (int e1 = 0; e1 < 2; e1++) {
                    float s = cAcc[nt][e1];
                    s += __shfl_xor_sync(0xFFFFFFFFu, s, 4);
                    s += __shfl_xor_sync(0xFFFFFFFFu, s, 8);
                    s += __shfl_xor_sync(0xFFFFFFFFu, s, 16);
                    if ((lane >> 2) == 0)
                        atomicAdd(&g_sumexp[J * 128 + wn + nt * 8 + 2 * (lane & 3) + e1], s);
                    cAcc[nt][e1] = 0.f;
                }
        }
        __syncthreads();
    }

    // ---- row-sum flush for both segments
#pragma unroll
    for (int seg = 0; seg < 2; seg++) {
        int Irow = seg ? I1 : I0;
#pragma unroll
        for (int mt = 0; mt < 2; mt++)
#pragma unroll
            for (int h = 0; h < 2; h++) {
                float v = rAccS[seg][mt][h];
                v += __shfl_xor_sync(0xFFFFFFFFu, v, 1);
                v += __shfl_xor_sync(0xFFFFFFFFu, v, 2);
                if ((lane & 3) == 0)
                    atomicAdd(&g_sumexp[Irow * 128 + wm + mt * 16 + h * 8 + (lane >> 2)], v);
            }
    }
}

// ------------------------------------------------------------- K3
__global__ void ntx_finalize(float* __restrict__ out, int Bv) {
    const int Nv = 2 * Bv;
    __shared__ float red[256];
    float acc = 0.f;
    for (int r = threadIdx.x; r < Nv; r += blockDim.x)
        acc += (logf(g_sumexp[r]) - g_pos[r]);
    red[threadIdx.x] = acc;
    __syncthreads();
    for (int s = 128; s > 0; s >>= 1) {
        if (threadIdx.x < s) red[threadIdx.x] += red[threadIdx.x + s];
        __syncthreads();
    }
    if (threadIdx.x == 0) out[0] = red[0] / (float)Nv;
}

// ------------------------------------------------------------- launch
extern "C" void kernel_launch(void* const* d_in, const int* in_sizes, int n_in,
                              void* d_out, int out_size) {
    const float* zi = (const float*)d_in[0];
    const float* zj = (const float*)d_in[1];
    const int Bv = in_sizes[0] / D_DIM;   // 4096
    const int Nv = 2 * Bv;                // 8192

    cudaFuncSetAttribute(ntx_simloss, cudaFuncAttributeMaxDynamicSharedMemorySize, SMEM_REQ);

    ntx_normalize<<<Nv / 8, 256>>>(zi, zj, Bv);   // 1024 blocks: covers zeroing too
    ntx_simloss<<<128, 256, SMEM_REQ>>>(Bv);      // 32 strips x 4
    ntx_finalize<<<1, 256>>>((float*)d_out, Bv);
}